// round 15
// baseline (speedup 1.0000x reference)
#include <cuda_runtime.h>
#include <cuda_fp16.h>
#include <cstdint>
#include <math.h>

using std::uint32_t;

// ---------------- problem constants ----------------
#define S_LEN 2048
#define HID   2048
#define NH    16
#define HD    128
#define NQKV  6144   // 3 * HID
#define ROT   32

// ---------------- scratch (device globals; no runtime alloc) ----------------
__device__ __half g_a[(size_t)S_LEN * HID];
__device__ __half g_b[(size_t)HID * NQKV];
__device__ __half g_w[(size_t)HID * HID];
__device__ __half g_c[(size_t)S_LEN * HID];

__device__ __half g_qf[(size_t)NH * S_LEN * HD];   // roped, scaled by log2e/sqrt(hd)
__device__ __half g_kf[(size_t)NH * S_LEN * HD];   // roped
__device__ __half g_vf[(size_t)NH * S_LEN * HD];

// ---------------- common PTX helpers ----------------
__device__ __forceinline__ void cp_async16(void* smem_dst, const void* gmem_src) {
    uint32_t s = (uint32_t)__cvta_generic_to_shared(smem_dst);
    asm volatile("cp.async.cg.shared.global [%0], [%1], 16;\n" :: "r"(s), "l"(gmem_src));
}
__device__ __forceinline__ void cp_commit() {
    asm volatile("cp.async.commit_group;\n");
}
template <int N>
__device__ __forceinline__ void cp_wait() {
    asm volatile("cp.async.wait_group %0;\n" :: "n"(N));
}

__device__ __forceinline__ void mma16816(float* c, const uint32_t* a, const uint32_t* b) {
    asm volatile(
        "mma.sync.aligned.m16n8k16.row.col.f32.f16.f16.f32 "
        "{%0,%1,%2,%3}, {%4,%5,%6,%7}, {%8,%9}, {%0,%1,%2,%3};\n"
        : "+f"(c[0]), "+f"(c[1]), "+f"(c[2]), "+f"(c[3])
        : "r"(a[0]), "r"(a[1]), "r"(a[2]), "r"(a[3]), "r"(b[0]), "r"(b[1]));
}

__device__ __forceinline__ void ldmx4(uint32_t* r, const void* p) {
    uint32_t a = (uint32_t)__cvta_generic_to_shared(p);
    asm volatile("ldmatrix.sync.aligned.m8n8.x4.shared.b16 {%0,%1,%2,%3}, [%4];"
                 : "=r"(r[0]), "=r"(r[1]), "=r"(r[2]), "=r"(r[3]) : "r"(a));
}
__device__ __forceinline__ void ldmx4t(uint32_t* r, const void* p) {
    uint32_t a = (uint32_t)__cvta_generic_to_shared(p);
    asm volatile("ldmatrix.sync.aligned.m8n8.x4.trans.shared.b16 {%0,%1,%2,%3}, [%4];"
                 : "=r"(r[0]), "=r"(r[1]), "=r"(r[2]), "=r"(r[3]) : "r"(a));
}

// ---------------- fp32 -> fp16 convert ----------------
__global__ __launch_bounds__(256) void to_fp16_kernel(
    const float* __restrict__ x, __half* __restrict__ y, int n4)
{
    int i = blockIdx.x * blockDim.x + threadIdx.x;
    if (i >= n4) return;
    float4 v = reinterpret_cast<const float4*>(x)[i];
    __half2* yp = reinterpret_cast<__half2*>(y);
    yp[2 * i]     = __floats2half2_rn(v.x, v.y);
    yp[2 * i + 1] = __floats2half2_rn(v.z, v.w);
}

// ---------------- GEMM tiling constants ----------------
#define GBK 64
#define SA     72
#define SB     136
#define OA     0
#define OB     (128 * SA)
#define BUFSZ  (OB + GBK * SB)       // 17920 halfs = 35840 B
#define GEMM_SMEM (3 * BUFSZ * 2)    // 107520 B

// fragment load for one k16 step (shared by both GEMMs)
#define LOAD_FRAGS(buf, kk, aF, bF)                                        \
    do {                                                                   \
        _Pragma("unroll")                                                  \
        for (int i = 0; i < 2; i++) {                                      \
            int ra = (warp_m * 32 + i * 16 + a_row) * SA + (kk) + a_colh;  \
            ldmx4((aF)[i], (buf) + OA + ra);                               \
        }                                                                  \
        _Pragma("unroll")                                                  \
        for (int jp = 0; jp < 4; jp++) {                                   \
            int rb = ((kk) + b_row) * SB + warp_n * 64 + jp * 16 + b_colh; \
            ldmx4t((bF)[jp], (buf) + OB + rb);                             \
        }                                                                  \
    } while (0)

#define DO_MMAS(aF, bF)                                                    \
    do {                                                                   \
        _Pragma("unroll")                                                  \
        for (int jp = 0; jp < 4; jp++) {                                   \
            uint32_t b0[2] = {(bF)[jp][0], (bF)[jp][1]};                   \
            uint32_t b1[2] = {(bF)[jp][2], (bF)[jp][3]};                   \
            _Pragma("unroll")                                              \
            for (int i = 0; i < 2; i++) {                                  \
                mma16816(acc[i][2 * jp],     (aF)[i], b0);                 \
                mma16816(acc[i][2 * jp + 1], (aF)[i], b1);                 \
            }                                                              \
        }                                                                  \
    } while (0)

// GEMM main loop with register-level fragment double-buffering
#define GEMM_MAINLOOP()                                                    \
    issue(0); cp_commit();                                                 \
    issue(1); cp_commit();                                                 \
    for (int s = 0; s < nst; s++) {                                        \
        cp_wait<1>();                                                      \
        __syncthreads();                                                   \
        if (s + 2 < nst) { issue(s + 2); cp_commit(); }                    \
        const __half* buf = sm + (s % 3) * BUFSZ;                          \
        uint32_t aF[2][2][4], bF[2][4][4];                                 \
        LOAD_FRAGS(buf, 0, aF[0], bF[0]);                                  \
        _Pragma("unroll")                                                  \
        for (int ks16 = 0; ks16 < 4; ks16++) {                             \
            int cur = ks16 & 1;                                            \
            if (ks16 < 3)                                                  \
                LOAD_FRAGS(buf, (ks16 + 1) * 16, aF[cur ^ 1], bF[cur ^ 1]);\
            DO_MMAS(aF[cur], bF[cur]);                                     \
        }                                                                  \
    }

// ---------------- QKV GEMM + bias + RoPE + head-major scatter ----------------
__global__ __launch_bounds__(256, 2) void qkv_gemm_rope(
    const __half* __restrict__ A, const __half* __restrict__ B,
    const float* __restrict__ bias,
    __half* __restrict__ Qp, __half* __restrict__ Kp, __half* __restrict__ Vp)
{
    extern __shared__ __align__(16) unsigned char smraw[];
    __half* sm = reinterpret_cast<__half*>(smraw);

    const int bx = blockIdx.x;
    const int by = blockIdx.y;
    const int tid = threadIdx.x;
    const int warp = tid >> 5;
    const int lane = tid & 31;
    const int warp_m = warp & 3;
    const int warp_n = warp >> 2;
    const int g  = lane >> 2;
    const int tg = lane & 3;
    const int K = HID, N = NQKV;
    const int nst = K / GBK;

    float acc[2][8][4];
    #pragma unroll
    for (int i = 0; i < 2; i++)
        #pragma unroll
        for (int j = 0; j < 8; j++)
            #pragma unroll
            for (int x = 0; x < 4; x++) acc[i][j][x] = 0.0f;

    auto issue = [&](int s) {
        const int k0 = s * GBK;
        __half* buf = sm + (s % 3) * BUFSZ;
        #pragma unroll
        for (int p = 0; p < 4; p++) {
            int q = tid + p * 256;
            int r = q >> 3, c = q & 7;
            size_t ga = (size_t)(by * 128 + r) * K + k0 + c * 8;
            cp_async16(buf + OA + r * SA + c * 8, A + ga);
        }
        #pragma unroll
        for (int p = 0; p < 4; p++) {
            int q = tid + p * 256;
            int r = q >> 4, c = q & 15;
            size_t gb = (size_t)(k0 + r) * N + bx * 128 + c * 8;
            cp_async16(buf + OB + r * SB + c * 8, B + gb);
        }
    };

    const int a_row = lane & 15;
    const int a_colh = (lane >> 4) << 3;
    const int b_row = lane & 15;
    const int b_colh = (lane >> 4) << 3;

    GEMM_MAINLOOP();

    // ---- epilogue: bias, RoPE (q/k), scale (q), head-major scatter ----
    const int head = bx / 3;
    const int sel  = bx - head * 3;      // 0=q, 1=k, 2=v
    __half* dst = (sel == 0) ? Qp : (sel == 1) ? Kp : Vp;
    // fold log2(e) into q scale so flash can use exp2
    const float qscale = 0.08838834764831845f * 1.44269504088896f;

    #pragma unroll
    for (int i = 0; i < 2; i++)
        #pragma unroll
        for (int j = 0; j < 8; j++) {
            int col = bx * 128 + warp_n * 64 + j * 8 + tg * 2;
            float b0 = bias[col], b1 = bias[col + 1];
            acc[i][j][0] += b0; acc[i][j][1] += b1;
            acc[i][j][2] += b0; acc[i][j][3] += b1;
        }

    if (sel < 2 && warp_n == 0) {
        #pragma unroll
        for (int i = 0; i < 2; i++) {
            int r0 = by * 128 + warp_m * 32 + i * 16 + g;
            #pragma unroll
            for (int j = 0; j < 2; j++) {
                #pragma unroll
                for (int e = 0; e < 2; e++) {
                    int d = j * 8 + tg * 2 + e;
                    float invf = powf(10000.0f, -(float)(2 * d) / 32.0f);
                    float s0, c0, s1, c1;
                    sincosf((float)r0 * invf, &s0, &c0);
                    sincosf((float)(r0 + 8) * invf, &s1, &c1);
                    float x1a = acc[i][j][e],     x2a = acc[i][j + 2][e];
                    float x1b = acc[i][j][e + 2], x2b = acc[i][j + 2][e + 2];
                    acc[i][j][e]         = x1a * c0 - x2a * s0;
                    acc[i][j + 2][e]     = x2a * c0 + x1a * s0;
                    acc[i][j][e + 2]     = x1b * c1 - x2b * s1;
                    acc[i][j + 2][e + 2] = x2b * c1 + x1b * s1;
                }
            }
        }
    }

    if (sel == 0) {
        #pragma unroll
        for (int i = 0; i < 2; i++)
            #pragma unroll
            for (int j = 0; j < 8; j++)
                #pragma unroll
                for (int x = 0; x < 4; x++) acc[i][j][x] *= qscale;
    }

    #pragma unroll
    for (int i = 0; i < 2; i++) {
        int row0 = by * 128 + warp_m * 32 + i * 16 + g;
        #pragma unroll
        for (int j = 0; j < 8; j++) {
            int d = warp_n * 64 + j * 8 + tg * 2;
            size_t o0 = ((size_t)head * S_LEN + row0) * HD + d;
            size_t o1 = ((size_t)head * S_LEN + row0 + 8) * HD + d;
            *reinterpret_cast<__half2*>(dst + o0) =
                __floats2half2_rn(acc[i][j][0], acc[i][j][1]);
            *reinterpret_cast<__half2*>(dst + o1) =
                __floats2half2_rn(acc[i][j][2], acc[i][j][3]);
        }
    }
}

// ---------------- dense GEMM (fp16 in, fp32 out + bias) ----------------
__global__ __launch_bounds__(256, 2) void mma_gemm_dense(
    const __half* __restrict__ A, const __half* __restrict__ B,
    const float* __restrict__ bias, float* __restrict__ C)
{
    extern __shared__ __align__(16) unsigned char smraw[];
    __half* sm = reinterpret_cast<__half*>(smraw);

    const int bx = blockIdx.x;
    const int by = blockIdx.y;
    const int tid = threadIdx.x;
    const int warp = tid >> 5;
    const int lane = tid & 31;
    const int warp_m = warp & 3;
    const int warp_n = warp >> 2;
    const int g  = lane >> 2;
    const int tg = lane & 3;
    const int K = HID, N = HID;
    const int nst = K / GBK;

    float acc[2][8][4];
    #pragma unroll
    for (int i = 0; i < 2; i++)
        #pragma unroll
        for (int j = 0; j < 8; j++)
            #pragma unroll
            for (int x = 0; x < 4; x++) acc[i][j][x] = 0.0f;

    auto issue = [&](int s) {
        const int k0 = s * GBK;
        __half* buf = sm + (s % 3) * BUFSZ;
        #pragma unroll
        for (int p = 0; p < 4; p++) {
            int q = tid + p * 256;
            int r = q >> 3, c = q & 7;
            size_t ga = (size_t)(by * 128 + r) * K + k0 + c * 8;
            cp_async16(buf + OA + r * SA + c * 8, A + ga);
        }
        #pragma unroll
        for (int p = 0; p < 4; p++) {
            int q = tid + p * 256;
            int r = q >> 4, c = q & 15;
            size_t gb = (size_t)(k0 + r) * N + bx * 128 + c * 8;
            cp_async16(buf + OB + r * SB + c * 8, B + gb);
        }
    };

    const int a_row = lane & 15;
    const int a_colh = (lane >> 4) << 3;
    const int b_row = lane & 15;
    const int b_colh = (lane >> 4) << 3;

    GEMM_MAINLOOP();

    #pragma unroll
    for (int i = 0; i < 2; i++) {
        #pragma unroll
        for (int j = 0; j < 8; j++) {
            int row0 = by * 128 + warp_m * 32 + i * 16 + g;
            int col  = bx * 128 + warp_n * 64 + j * 8 + tg * 2;
            float b0 = bias[col], b1 = bias[col + 1];
            *reinterpret_cast<float2*>(C + (size_t)row0 * N + col) =
                make_float2(acc[i][j][0] + b0, acc[i][j][1] + b1);
            *reinterpret_cast<float2*>(C + (size_t)(row0 + 8) * N + col) =
                make_float2(acc[i][j][2] + b0, acc[i][j][3] + b1);
        }
    }
}

// ---------------- HMMA flash attention (fp16, causal, FBN=128, exp2) ----------------
#define FBM 128
#define FBN 128
#define FSTR 136

#define FQ   0
#define FKV0 (128 * FSTR)
#define KVARR (128 * FSTR)
#define KVSTG (2 * KVARR)
#define FLASH_SMEM ((FKV0 + 2 * KVSTG) * 2)   // 174080 B

__global__ __launch_bounds__(256, 1) void flash_mma_kernel(
    const __half* __restrict__ Q, const __half* __restrict__ K,
    const __half* __restrict__ V, __half* __restrict__ Cf)
{
    extern __shared__ __align__(16) unsigned char fsraw[];
    __half* fs = reinterpret_cast<__half*>(fsraw);

    const int h = blockIdx.y;
    const int m_tile = gridDim.x - 1 - blockIdx.x;
    const int m0 = m_tile * FBM;
    const int tid = threadIdx.x;
    const int warp = tid >> 5;
    const int lane = tid & 31;
    const int g  = lane >> 2;
    const int tg = lane & 3;

    const __half* qp = Q + ((size_t)h * S_LEN + m0) * HD;
    const __half* kp = K + (size_t)h * S_LEN * HD;
    const __half* vp = V + (size_t)h * S_LEN * HD;

    for (int idx = tid; idx < 2048; idx += 256) {
        int r = idx >> 4, c = (idx & 15) << 3;
        *reinterpret_cast<float4*>(fs + FQ + r * FSTR + c) =
            *reinterpret_cast<const float4*>(qp + (size_t)r * HD + c);
    }

    auto issue_kv = [&](int nt) {
        const int n0 = nt * FBN;
        __half* buf = fs + FKV0 + (nt & 1) * KVSTG;
        #pragma unroll
        for (int q = tid; q < 2048; q += 256) {
            int r = q >> 4, c = (q & 15) << 3;
            size_t go = (size_t)(n0 + r) * HD + c;
            int so = r * FSTR + c;
            cp_async16(buf + 0 * KVARR + so, kp + go);
            cp_async16(buf + 1 * KVARR + so, vp + go);
        }
    };

    float o[16][4];
    #pragma unroll
    for (int j = 0; j < 16; j++)
        #pragma unroll
        for (int x = 0; x < 4; x++) o[j][x] = 0.0f;
    float mrow0 = -1e30f, mrow1 = -1e30f, lrow0 = 0.0f, lrow1 = 0.0f;

    const int row0 = m0 + warp * 16 + g;
    const int row1 = row0 + 8;

    const int a_row = lane & 15;
    const int half8 = (lane >> 4) << 3;
    const int bk_colh = ((lane >> 3) & 1) << 3;

    const int ntiles = m0 / FBN + 1;
    issue_kv(0); cp_commit();

    for (int nt = 0; nt < ntiles; nt++) {
        const int n0 = nt * FBN;
        if (nt + 1 < ntiles) { issue_kv(nt + 1); cp_commit(); cp_wait<1>(); }
        else                 { cp_wait<0>(); }
        __syncthreads();

        const __half* kvb = fs + FKV0 + (nt & 1) * KVSTG;
        const __half* k_s = kvb;
        const __half* v_s = kvb + KVARR;

        float sacc[16][4];
        #pragma unroll
        for (int j = 0; j < 16; j++)
            #pragma unroll
            for (int x = 0; x < 4; x++) sacc[j][x] = 0.0f;

        #pragma unroll
        for (int ks = 0; ks < 8; ks++) {
            const int k = ks * 16;
            uint32_t aF[4];
            {
                int ra = (warp * 16 + a_row) * FSTR + k + half8;
                ldmx4(aF, fs + FQ + ra);
            }
            #pragma unroll
            for (int jp = 0; jp < 8; jp++) {
                int rb = (jp * 16 + half8 + (lane & 7)) * FSTR + k + bk_colh;
                uint32_t bF[4];
                ldmx4(bF, k_s + rb);
                uint32_t b0[2] = {bF[0], bF[1]}, b1[2] = {bF[2], bF[3]};
                mma16816(sacc[2 * jp],     aF, b0);
                mma16816(sacc[2 * jp + 1], aF, b1);
            }
        }

        if (nt == ntiles - 1) {
            #pragma unroll
            for (int j = 0; j < 16; j++) {
                int c0 = n0 + j * 8 + 2 * tg;
                if (c0     > row0) sacc[j][0] = -1e30f;
                if (c0 + 1 > row0) sacc[j][1] = -1e30f;
                if (c0     > row1) sacc[j][2] = -1e30f;
                if (c0 + 1 > row1) sacc[j][3] = -1e30f;
            }
        }

        float mx0 = -1e30f, mx1 = -1e30f;
        #pragma unroll
        for (int j = 0; j < 16; j++) {
            mx0 = fmaxf(mx0, fmaxf(sacc[j][0], sacc[j][1]));
            mx1 = fmaxf(mx1, fmaxf(sacc[j][2], sacc[j][3]));
        }
        mx0 = fmaxf(mx0, __shfl_xor_sync(0xffffffffu, mx0, 1));
        mx0 = fmaxf(mx0, __shfl_xor_sync(0xffffffffu, mx0, 2));
        mx1 = fmaxf(mx1, __shfl_xor_sync(0xffffffffu, mx1, 1));
        mx1 = fmaxf(mx1, __shfl_xor_sync(0xffffffffu, mx1, 2));

        float mn0 = fmaxf(mrow0, mx0);
        float mn1 = fmaxf(mrow1, mx1);
        float alpha0 = exp2f(mrow0 - mn0);
        float alpha1 = exp2f(mrow1 - mn1);
        mrow0 = mn0; mrow1 = mn1;

        float sum0 = 0.0f, sum1 = 0.0f;
        #pragma unroll
        for (int j = 0; j < 16; j++) {
            sacc[j][0] = exp2f(sacc[j][0] - mn0);
            sacc[j][1] = exp2f(sacc[j][1] - mn0);
            sacc[j][2] = exp2f(sacc[j][2] - mn1);
            sacc[j][3] = exp2f(sacc[j][3] - mn1);
            sum0 += sacc[j][0] + sacc[j][1];
            sum1 += sacc[j][2] + sacc[j][3];
        }
        sum0 += __shfl_xor_sync(0xffffffffu, sum0, 1);
        sum0 += __shfl_xor_sync(0xffffffffu, sum0, 2);
        sum1 += __shfl_xor_sync(0xffffffffu, sum1, 1);
        sum1 += __shfl_xor_sync(0xffffffffu, sum1, 2);
        lrow0 = lrow0 * alpha0 + sum0;
        lrow1 = lrow1 * alpha1 + sum1;

        #pragma unroll
        for (int j = 0; j < 16; j++) {
            o[j][0] *= alpha0; o[j][1] *= alpha0;
            o[j][2] *= alpha1; o[j][3] *= alpha1;
        }

        #pragma unroll
        for (int kk = 0; kk < 8; kk++) {
            uint32_t pa[4];
            #pragma unroll
            for (int half = 0; half < 2; half++) {
                const float* sv = sacc[2 * kk + half];
                __half2 h0 = __floats2half2_rn(sv[0], sv[1]);
                __half2 h1 = __floats2half2_rn(sv[2], sv[3]);
                pa[2 * half]     = *reinterpret_cast<uint32_t*>(&h0);
                pa[2 * half + 1] = *reinterpret_cast<uint32_t*>(&h1);
            }
            #pragma unroll
            for (int jp = 0; jp < 8; jp++) {
                int rv = (kk * 16 + a_row) * FSTR + jp * 16 + half8;
                uint32_t vF[4];
                ldmx4t(vF, v_s + rv);
                uint32_t v0[2] = {vF[0], vF[1]}, v1[2] = {vF[2], vF[3]};
                mma16816(o[2 * jp],     pa, v0);
                mma16816(o[2 * jp + 1], pa, v1);
            }
        }
        __syncthreads();
    }

    float inv0 = 1.0f / lrow0;
    float inv1 = 1.0f / lrow1;
    #pragma unroll
    for (int jt = 0; jt < 16; jt++) {
        int col = h * HD + jt * 8 + 2 * tg;
        __half2 r0 = __floats2half2_rn(o[jt][0] * inv0, o[jt][1] * inv0);
        __half2 r1 = __floats2half2_rn(o[jt][2] * inv1, o[jt][3] * inv1);
        *reinterpret_cast<__half2*>(Cf + (size_t)row0 * HID + col) = r0;
        *reinterpret_cast<__half2*>(Cf + (size_t)row1 * HID + col) = r1;
    }
}

// ---------------- launch ----------------
extern "C" void kernel_launch(void* const* d_in, const int* in_sizes, int n_in,
                              void* d_out, int out_size)
{
    const float* hidden  = (const float*)d_in[0];
    const float* W_qkv   = (const float*)d_in[1];
    const float* b_qkv   = (const float*)d_in[2];
    const float* W_dense = (const float*)d_in[3];
    const float* b_dense = (const float*)d_in[4];
    float* out = (float*)d_out;

    __half *a, *b, *w, *c, *qf, *kf, *vf;
    cudaGetSymbolAddress((void**)&a,  g_a);
    cudaGetSymbolAddress((void**)&b,  g_b);
    cudaGetSymbolAddress((void**)&w,  g_w);
    cudaGetSymbolAddress((void**)&c,  g_c);
    cudaGetSymbolAddress((void**)&qf, g_qf);
    cudaGetSymbolAddress((void**)&kf, g_kf);
    cudaGetSymbolAddress((void**)&vf, g_vf);

    cudaFuncSetAttribute(qkv_gemm_rope,
                         cudaFuncAttributeMaxDynamicSharedMemorySize, GEMM_SMEM);
    cudaFuncSetAttribute(mma_gemm_dense,
                         cudaFuncAttributeMaxDynamicSharedMemorySize, GEMM_SMEM);
    cudaFuncSetAttribute(flash_mma_kernel,
                         cudaFuncAttributeMaxDynamicSharedMemorySize, FLASH_SMEM);

    // 0) fp16 conversions
    {
        int n4 = S_LEN * HID / 4;
        to_fp16_kernel<<<(n4 + 255) / 256, 256>>>(hidden, a, n4);
        int w4 = HID * NQKV / 4;
        to_fp16_kernel<<<(w4 + 255) / 256, 256>>>(W_qkv, b, w4);
        int d4 = HID * HID / 4;
        to_fp16_kernel<<<(d4 + 255) / 256, 256>>>(W_dense, w, d4);
    }

    // 1) QKV projection + bias + RoPE + scatter
    {
        dim3 grid(NQKV / 128, S_LEN / 128);
        qkv_gemm_rope<<<grid, 256, GEMM_SMEM>>>(a, b, b_qkv, qf, kf, vf);
    }

    // 2) causal flash attention (exp2 softmax)
    flash_mma_kernel<<<dim3(S_LEN / FBM, NH), 256, FLASH_SMEM>>>(qf, kf, vf, c);

    // 3) dense projection (+bias) -> fp32 out
    {
        dim3 grid(HID / 128, S_LEN / 128);
        mma_gemm_dense<<<grid, 256, GEMM_SMEM>>>(c, w, b_dense, out);
    }
}

// round 16
// speedup vs baseline: 1.0254x; 1.0254x over previous
#include <cuda_runtime.h>
#include <cuda_fp16.h>
#include <cstdint>
#include <math.h>

using std::uint32_t;

// ---------------- problem constants ----------------
#define S_LEN 2048
#define HID   2048
#define NH    16
#define HD    128
#define NQKV  6144   // 3 * HID
#define ROT   32

// ---------------- scratch (device globals; no runtime alloc) ----------------
__device__ __half g_a[(size_t)S_LEN * HID];
__device__ __half g_b[(size_t)HID * NQKV];
__device__ __half g_w[(size_t)HID * HID];
__device__ __half g_c[(size_t)S_LEN * HID];

__device__ __half g_qf[(size_t)NH * S_LEN * HD];   // roped, scaled by log2e/sqrt(hd)
__device__ __half g_kf[(size_t)NH * S_LEN * HD];   // roped
__device__ __half g_vf[(size_t)NH * S_LEN * HD];

// ---------------- common PTX helpers ----------------
__device__ __forceinline__ void cp_async16(void* smem_dst, const void* gmem_src) {
    uint32_t s = (uint32_t)__cvta_generic_to_shared(smem_dst);
    asm volatile("cp.async.cg.shared.global [%0], [%1], 16;\n" :: "r"(s), "l"(gmem_src));
}
__device__ __forceinline__ void cp_commit() {
    asm volatile("cp.async.commit_group;\n");
}
template <int N>
__device__ __forceinline__ void cp_wait() {
    asm volatile("cp.async.wait_group %0;\n" :: "n"(N));
}

__device__ __forceinline__ void mma16816(float* c, const uint32_t* a, const uint32_t* b) {
    asm volatile(
        "mma.sync.aligned.m16n8k16.row.col.f32.f16.f16.f32 "
        "{%0,%1,%2,%3}, {%4,%5,%6,%7}, {%8,%9}, {%0,%1,%2,%3};\n"
        : "+f"(c[0]), "+f"(c[1]), "+f"(c[2]), "+f"(c[3])
        : "r"(a[0]), "r"(a[1]), "r"(a[2]), "r"(a[3]), "r"(b[0]), "r"(b[1]));
}

__device__ __forceinline__ void ldmx4(uint32_t* r, const void* p) {
    uint32_t a = (uint32_t)__cvta_generic_to_shared(p);
    asm volatile("ldmatrix.sync.aligned.m8n8.x4.shared.b16 {%0,%1,%2,%3}, [%4];"
                 : "=r"(r[0]), "=r"(r[1]), "=r"(r[2]), "=r"(r[3]) : "r"(a));
}
__device__ __forceinline__ void ldmx4t(uint32_t* r, const void* p) {
    uint32_t a = (uint32_t)__cvta_generic_to_shared(p);
    asm volatile("ldmatrix.sync.aligned.m8n8.x4.trans.shared.b16 {%0,%1,%2,%3}, [%4];"
                 : "=r"(r[0]), "=r"(r[1]), "=r"(r[2]), "=r"(r[3]) : "r"(a));
}

// ---------------- fp32 -> fp16 convert ----------------
__global__ __launch_bounds__(256) void to_fp16_kernel(
    const float* __restrict__ x, __half* __restrict__ y, int n4)
{
    int i = blockIdx.x * blockDim.x + threadIdx.x;
    if (i >= n4) return;
    float4 v = reinterpret_cast<const float4*>(x)[i];
    __half2* yp = reinterpret_cast<__half2*>(y);
    yp[2 * i]     = __floats2half2_rn(v.x, v.y);
    yp[2 * i + 1] = __floats2half2_rn(v.z, v.w);
}

// ---------------- GEMM tiling constants ----------------
#define GBK 64
#define SA     72
#define SB     136
#define OA     0
#define OB     (128 * SA)
#define BUFSZ  (OB + GBK * SB)       // 17920 halfs = 35840 B
#define GEMM_SMEM (3 * BUFSZ * 2)    // 107520 B

// ---------------- QKV GEMM + bias + RoPE + head-major scatter ----------------
__global__ __launch_bounds__(256, 2) void qkv_gemm_rope(
    const __half* __restrict__ A, const __half* __restrict__ B,
    const float* __restrict__ bias,
    __half* __restrict__ Qp, __half* __restrict__ Kp, __half* __restrict__ Vp)
{
    extern __shared__ __align__(16) unsigned char smraw[];
    __half* sm = reinterpret_cast<__half*>(smraw);

    const int bx = blockIdx.x;
    const int by = blockIdx.y;
    const int tid = threadIdx.x;
    const int warp = tid >> 5;
    const int lane = tid & 31;
    const int warp_m = warp & 3;
    const int warp_n = warp >> 2;
    const int g  = lane >> 2;
    const int tg = lane & 3;
    const int K = HID, N = NQKV;
    const int nst = K / GBK;

    float acc[2][8][4];
    #pragma unroll
    for (int i = 0; i < 2; i++)
        #pragma unroll
        for (int j = 0; j < 8; j++)
            #pragma unroll
            for (int x = 0; x < 4; x++) acc[i][j][x] = 0.0f;

    auto issue = [&](int s) {
        const int k0 = s * GBK;
        __half* buf = sm + (s % 3) * BUFSZ;
        #pragma unroll
        for (int p = 0; p < 4; p++) {
            int q = tid + p * 256;
            int r = q >> 3, c = q & 7;
            size_t ga = (size_t)(by * 128 + r) * K + k0 + c * 8;
            cp_async16(buf + OA + r * SA + c * 8, A + ga);
        }
        #pragma unroll
        for (int p = 0; p < 4; p++) {
            int q = tid + p * 256;
            int r = q >> 4, c = q & 15;
            size_t gb = (size_t)(k0 + r) * N + bx * 128 + c * 8;
            cp_async16(buf + OB + r * SB + c * 8, B + gb);
        }
    };

    issue(0); cp_commit();
    issue(1); cp_commit();

    const int a_row = lane & 15;
    const int a_colh = (lane >> 4) << 3;
    const int b_row = lane & 15;
    const int b_colh = (lane >> 4) << 3;

    for (int s = 0; s < nst; s++) {
        cp_wait<1>();
        __syncthreads();
        if (s + 2 < nst) { issue(s + 2); cp_commit(); }

        const __half* buf = sm + (s % 3) * BUFSZ;

        #pragma unroll
        for (int ks = 0; ks < GBK; ks += 16) {
            uint32_t ah[2][4];
            #pragma unroll
            for (int i = 0; i < 2; i++) {
                int ra = (warp_m * 32 + i * 16 + a_row) * SA + ks + a_colh;
                ldmx4(ah[i], buf + OA + ra);
            }
            #pragma unroll
            for (int jp = 0; jp < 4; jp++) {
                int rb = (ks + b_row) * SB + warp_n * 64 + jp * 16 + b_colh;
                uint32_t th[4];
                ldmx4t(th, buf + OB + rb);
                uint32_t b0[2] = {th[0], th[1]}, b1[2] = {th[2], th[3]};
                #pragma unroll
                for (int i = 0; i < 2; i++) {
                    mma16816(acc[i][2 * jp],     ah[i], b0);
                    mma16816(acc[i][2 * jp + 1], ah[i], b1);
                }
            }
        }
    }

    // ---- epilogue: bias, RoPE (q/k), scale (q), head-major scatter ----
    const int head = bx / 3;
    const int sel  = bx - head * 3;      // 0=q, 1=k, 2=v
    __half* dst = (sel == 0) ? Qp : (sel == 1) ? Kp : Vp;
    const float qscale = 0.08838834764831845f * 1.44269504088896f;  // log2e folded

    #pragma unroll
    for (int i = 0; i < 2; i++)
        #pragma unroll
        for (int j = 0; j < 8; j++) {
            int col = bx * 128 + warp_n * 64 + j * 8 + tg * 2;
            float b0 = bias[col], b1 = bias[col + 1];
            acc[i][j][0] += b0; acc[i][j][1] += b1;
            acc[i][j][2] += b0; acc[i][j][3] += b1;
        }

    if (sel < 2 && warp_n == 0) {
        #pragma unroll
        for (int i = 0; i < 2; i++) {
            int r0 = by * 128 + warp_m * 32 + i * 16 + g;
            #pragma unroll
            for (int j = 0; j < 2; j++) {
                #pragma unroll
                for (int e = 0; e < 2; e++) {
                    int d = j * 8 + tg * 2 + e;
                    float invf = powf(10000.0f, -(float)(2 * d) / 32.0f);
                    float s0, c0, s1, c1;
                    sincosf((float)r0 * invf, &s0, &c0);
                    sincosf((float)(r0 + 8) * invf, &s1, &c1);
                    float x1a = acc[i][j][e],     x2a = acc[i][j + 2][e];
                    float x1b = acc[i][j][e + 2], x2b = acc[i][j + 2][e + 2];
                    acc[i][j][e]         = x1a * c0 - x2a * s0;
                    acc[i][j + 2][e]     = x2a * c0 + x1a * s0;
                    acc[i][j][e + 2]     = x1b * c1 - x2b * s1;
                    acc[i][j + 2][e + 2] = x2b * c1 + x1b * s1;
                }
            }
        }
    }

    if (sel == 0) {
        #pragma unroll
        for (int i = 0; i < 2; i++)
            #pragma unroll
            for (int j = 0; j < 8; j++)
                #pragma unroll
                for (int x = 0; x < 4; x++) acc[i][j][x] *= qscale;
    }

    #pragma unroll
    for (int i = 0; i < 2; i++) {
        int row0 = by * 128 + warp_m * 32 + i * 16 + g;
        #pragma unroll
        for (int j = 0; j < 8; j++) {
            int d = warp_n * 64 + j * 8 + tg * 2;
            size_t o0 = ((size_t)head * S_LEN + row0) * HD + d;
            size_t o1 = ((size_t)head * S_LEN + row0 + 8) * HD + d;
            *reinterpret_cast<__half2*>(dst + o0) =
                __floats2half2_rn(acc[i][j][0], acc[i][j][1]);
            *reinterpret_cast<__half2*>(dst + o1) =
                __floats2half2_rn(acc[i][j][2], acc[i][j][3]);
        }
    }
}

// ---------------- dense GEMM (fp16 in, fp32 out + bias) ----------------
__global__ __launch_bounds__(256, 2) void mma_gemm_dense(
    const __half* __restrict__ A, const __half* __restrict__ B,
    const float* __restrict__ bias, float* __restrict__ C)
{
    extern __shared__ __align__(16) unsigned char smraw[];
    __half* sm = reinterpret_cast<__half*>(smraw);

    const int bx = blockIdx.x;
    const int by = blockIdx.y;
    const int tid = threadIdx.x;
    const int warp = tid >> 5;
    const int lane = tid & 31;
    const int warp_m = warp & 3;
    const int warp_n = warp >> 2;
    const int g  = lane >> 2;
    const int tg = lane & 3;
    const int K = HID, N = HID;
    const int nst = K / GBK;

    float acc[2][8][4];
    #pragma unroll
    for (int i = 0; i < 2; i++)
        #pragma unroll
        for (int j = 0; j < 8; j++)
            #pragma unroll
            for (int x = 0; x < 4; x++) acc[i][j][x] = 0.0f;

    auto issue = [&](int s) {
        const int k0 = s * GBK;
        __half* buf = sm + (s % 3) * BUFSZ;
        #pragma unroll
        for (int p = 0; p < 4; p++) {
            int q = tid + p * 256;
            int r = q >> 3, c = q & 7;
            size_t ga = (size_t)(by * 128 + r) * K + k0 + c * 8;
            cp_async16(buf + OA + r * SA + c * 8, A + ga);
        }
        #pragma unroll
        for (int p = 0; p < 4; p++) {
            int q = tid + p * 256;
            int r = q >> 4, c = q & 15;
            size_t gb = (size_t)(k0 + r) * N + bx * 128 + c * 8;
            cp_async16(buf + OB + r * SB + c * 8, B + gb);
        }
    };

    issue(0); cp_commit();
    issue(1); cp_commit();

    const int a_row = lane & 15;
    const int a_colh = (lane >> 4) << 3;
    const int b_row = lane & 15;
    const int b_colh = (lane >> 4) << 3;

    for (int s = 0; s < nst; s++) {
        cp_wait<1>();
        __syncthreads();
        if (s + 2 < nst) { issue(s + 2); cp_commit(); }

        const __half* buf = sm + (s % 3) * BUFSZ;

        #pragma unroll
        for (int ks = 0; ks < GBK; ks += 16) {
            uint32_t ah[2][4];
            #pragma unroll
            for (int i = 0; i < 2; i++) {
                int ra = (warp_m * 32 + i * 16 + a_row) * SA + ks + a_colh;
                ldmx4(ah[i], buf + OA + ra);
            }
            #pragma unroll
            for (int jp = 0; jp < 4; jp++) {
                int rb = (ks + b_row) * SB + warp_n * 64 + jp * 16 + b_colh;
                uint32_t th[4];
                ldmx4t(th, buf + OB + rb);
                uint32_t b0[2] = {th[0], th[1]}, b1[2] = {th[2], th[3]};
                #pragma unroll
                for (int i = 0; i < 2; i++) {
                    mma16816(acc[i][2 * jp],     ah[i], b0);
                    mma16816(acc[i][2 * jp + 1], ah[i], b1);
                }
            }
        }
    }

    #pragma unroll
    for (int i = 0; i < 2; i++) {
        #pragma unroll
        for (int j = 0; j < 8; j++) {
            int row0 = by * 128 + warp_m * 32 + i * 16 + g;
            int col  = bx * 128 + warp_n * 64 + j * 8 + tg * 2;
            float b0 = bias[col], b1 = bias[col + 1];
            *reinterpret_cast<float2*>(C + (size_t)row0 * N + col) =
                make_float2(acc[i][j][0] + b0, acc[i][j][1] + b1);
            *reinterpret_cast<float2*>(C + (size_t)(row0 + 8) * N + col) =
                make_float2(acc[i][j][2] + b0, acc[i][j][3] + b1);
        }
    }
}

// ---------------- HMMA flash attention (fp16, causal) ----------------
// FBM=64, FBN=64, 128 threads (4 warps), 2 CTAs/SM for barrier overlap.
#define FBM 64
#define FBN 64
#define FSTR 136

#define FQ    0
#define FKV0  (64 * FSTR)            // 8704 halfs
#define KVARR (64 * FSTR)            // 8704 halfs per array
#define KVSTG (2 * KVARR)            // one stage: K, V
#define FLASH_SMEM ((FKV0 + 2 * KVSTG) * 2)   // 87040 B

__global__ __launch_bounds__(128, 2) void flash_mma_kernel(
    const __half* __restrict__ Q, const __half* __restrict__ K,
    const __half* __restrict__ V, __half* __restrict__ Cf)
{
    extern __shared__ __align__(16) unsigned char fsraw[];
    __half* fs = reinterpret_cast<__half*>(fsraw);

    const int h = blockIdx.y;
    const int m_tile = gridDim.x - 1 - blockIdx.x;   // long blocks first
    const int m0 = m_tile * FBM;
    const int tid = threadIdx.x;
    const int warp = tid >> 5;         // 0..3
    const int lane = tid & 31;
    const int g  = lane >> 2;
    const int tg = lane & 3;

    const __half* qp = Q + ((size_t)h * S_LEN + m0) * HD;
    const __half* kp = K + (size_t)h * S_LEN * HD;
    const __half* vp = V + (size_t)h * S_LEN * HD;

    // load Q tile: 64 rows x 16 chunks = 1024 chunks over 128 threads
    for (int idx = tid; idx < 1024; idx += 128) {
        int r = idx >> 4, c = (idx & 15) << 3;
        *reinterpret_cast<float4*>(fs + FQ + r * FSTR + c) =
            *reinterpret_cast<const float4*>(qp + (size_t)r * HD + c);
    }

    auto issue_kv = [&](int nt) {
        const int n0 = nt * FBN;
        __half* buf = fs + FKV0 + (nt & 1) * KVSTG;
        #pragma unroll
        for (int q = tid; q < 1024; q += 128) {
            int r = q >> 4, c = (q & 15) << 3;
            size_t go = (size_t)(n0 + r) * HD + c;
            int so = r * FSTR + c;
            cp_async16(buf + 0 * KVARR + so, kp + go);
            cp_async16(buf + 1 * KVARR + so, vp + go);
        }
    };

    float o[16][4];
    #pragma unroll
    for (int j = 0; j < 16; j++)
        #pragma unroll
        for (int x = 0; x < 4; x++) o[j][x] = 0.0f;
    float mrow0 = -1e30f, mrow1 = -1e30f, lrow0 = 0.0f, lrow1 = 0.0f;

    const int row0 = m0 + warp * 16 + g;
    const int row1 = row0 + 8;

    const int a_row = lane & 15;
    const int half8 = (lane >> 4) << 3;
    const int bk_colh = ((lane >> 3) & 1) << 3;

    const int ntiles = m0 / FBN + 1;
    issue_kv(0); cp_commit();

    for (int nt = 0; nt < ntiles; nt++) {
        const int n0 = nt * FBN;
        if (nt + 1 < ntiles) { issue_kv(nt + 1); cp_commit(); cp_wait<1>(); }
        else                 { cp_wait<0>(); }
        __syncthreads();

        const __half* kvb = fs + FKV0 + (nt & 1) * KVSTG;
        const __half* k_s = kvb;
        const __half* v_s = kvb + KVARR;

        float sacc[8][4];
        #pragma unroll
        for (int j = 0; j < 8; j++)
            #pragma unroll
            for (int x = 0; x < 4; x++) sacc[j][x] = 0.0f;

        #pragma unroll
        for (int ks = 0; ks < 8; ks++) {
            const int k = ks * 16;
            uint32_t aF[4];
            {
                int ra = (warp * 16 + a_row) * FSTR + k + half8;
                ldmx4(aF, fs + FQ + ra);
            }
            #pragma unroll
            for (int jp = 0; jp < 4; jp++) {
                int rb = (jp * 16 + half8 + (lane & 7)) * FSTR + k + bk_colh;
                uint32_t bF[4];
                ldmx4(bF, k_s + rb);
                uint32_t b0[2] = {bF[0], bF[1]}, b1[2] = {bF[2], bF[3]};
                mma16816(sacc[2 * jp],     aF, b0);
                mma16816(sacc[2 * jp + 1], aF, b1);
            }
        }

        // causal mask only on the diagonal (last) tile
        if (nt == ntiles - 1) {
            #pragma unroll
            for (int j = 0; j < 8; j++) {
                int c0 = n0 + j * 8 + 2 * tg;
                if (c0     > row0) sacc[j][0] = -1e30f;
                if (c0 + 1 > row0) sacc[j][1] = -1e30f;
                if (c0     > row1) sacc[j][2] = -1e30f;
                if (c0 + 1 > row1) sacc[j][3] = -1e30f;
            }
        }

        float mx0 = -1e30f, mx1 = -1e30f;
        #pragma unroll
        for (int j = 0; j < 8; j++) {
            mx0 = fmaxf(mx0, fmaxf(sacc[j][0], sacc[j][1]));
            mx1 = fmaxf(mx1, fmaxf(sacc[j][2], sacc[j][3]));
        }
        mx0 = fmaxf(mx0, __shfl_xor_sync(0xffffffffu, mx0, 1));
        mx0 = fmaxf(mx0, __shfl_xor_sync(0xffffffffu, mx0, 2));
        mx1 = fmaxf(mx1, __shfl_xor_sync(0xffffffffu, mx1, 1));
        mx1 = fmaxf(mx1, __shfl_xor_sync(0xffffffffu, mx1, 2));

        float mn0 = fmaxf(mrow0, mx0);
        float mn1 = fmaxf(mrow1, mx1);
        float alpha0 = exp2f(mrow0 - mn0);
        float alpha1 = exp2f(mrow1 - mn1);
        mrow0 = mn0; mrow1 = mn1;

        float sum0 = 0.0f, sum1 = 0.0f;
        #pragma unroll
        for (int j = 0; j < 8; j++) {
            sacc[j][0] = exp2f(sacc[j][0] - mn0);
            sacc[j][1] = exp2f(sacc[j][1] - mn0);
            sacc[j][2] = exp2f(sacc[j][2] - mn1);
            sacc[j][3] = exp2f(sacc[j][3] - mn1);
            sum0 += sacc[j][0] + sacc[j][1];
            sum1 += sacc[j][2] + sacc[j][3];
        }
        sum0 += __shfl_xor_sync(0xffffffffu, sum0, 1);
        sum0 += __shfl_xor_sync(0xffffffffu, sum0, 2);
        sum1 += __shfl_xor_sync(0xffffffffu, sum1, 1);
        sum1 += __shfl_xor_sync(0xffffffffu, sum1, 2);
        lrow0 = lrow0 * alpha0 + sum0;
        lrow1 = lrow1 * alpha1 + sum1;

        #pragma unroll
        for (int j = 0; j < 16; j++) {
            o[j][0] *= alpha0; o[j][1] *= alpha0;
            o[j][2] *= alpha1; o[j][3] *= alpha1;
        }

        #pragma unroll
        for (int kk = 0; kk < 4; kk++) {
            uint32_t pa[4];
            #pragma unroll
            for (int half = 0; half < 2; half++) {
                const float* sv = sacc[2 * kk + half];
                __half2 h0 = __floats2half2_rn(sv[0], sv[1]);
                __half2 h1 = __floats2half2_rn(sv[2], sv[3]);
                pa[2 * half]     = *reinterpret_cast<uint32_t*>(&h0);
                pa[2 * half + 1] = *reinterpret_cast<uint32_t*>(&h1);
            }
            #pragma unroll
            for (int jp = 0; jp < 8; jp++) {
                int rv = (kk * 16 + a_row) * FSTR + jp * 16 + half8;
                uint32_t vF[4];
                ldmx4t(vF, v_s + rv);
                uint32_t v0[2] = {vF[0], vF[1]}, v1[2] = {vF[2], vF[3]};
                mma16816(o[2 * jp],     pa, v0);
                mma16816(o[2 * jp + 1], pa, v1);
            }
        }
        __syncthreads();
    }

    float inv0 = 1.0f / lrow0;
    float inv1 = 1.0f / lrow1;
    #pragma unroll
    for (int jt = 0; jt < 16; jt++) {
        int col = h * HD + jt * 8 + 2 * tg;
        __half2 r0 = __floats2half2_rn(o[jt][0] * inv0, o[jt][1] * inv0);
        __half2 r1 = __floats2half2_rn(o[jt][2] * inv1, o[jt][3] * inv1);
        *reinterpret_cast<__half2*>(Cf + (size_t)row0 * HID + col) = r0;
        *reinterpret_cast<__half2*>(Cf + (size_t)row1 * HID + col) = r1;
    }
}

// ---------------- launch ----------------
extern "C" void kernel_launch(void* const* d_in, const int* in_sizes, int n_in,
                              void* d_out, int out_size)
{
    const float* hidden  = (const float*)d_in[0];
    const float* W_qkv   = (const float*)d_in[1];
    const float* b_qkv   = (const float*)d_in[2];
    const float* W_dense = (const float*)d_in[3];
    const float* b_dense = (const float*)d_in[4];
    float* out = (float*)d_out;

    __half *a, *b, *w, *c, *qf, *kf, *vf;
    cudaGetSymbolAddress((void**)&a,  g_a);
    cudaGetSymbolAddress((void**)&b,  g_b);
    cudaGetSymbolAddress((void**)&w,  g_w);
    cudaGetSymbolAddress((void**)&c,  g_c);
    cudaGetSymbolAddress((void**)&qf, g_qf);
    cudaGetSymbolAddress((void**)&kf, g_kf);
    cudaGetSymbolAddress((void**)&vf, g_vf);

    cudaFuncSetAttribute(qkv_gemm_rope,
                         cudaFuncAttributeMaxDynamicSharedMemorySize, GEMM_SMEM);
    cudaFuncSetAttribute(mma_gemm_dense,
                         cudaFuncAttributeMaxDynamicSharedMemorySize, GEMM_SMEM);
    cudaFuncSetAttribute(flash_mma_kernel,
                         cudaFuncAttributeMaxDynamicSharedMemorySize, FLASH_SMEM);

    // 0) fp16 conversions
    {
        int n4 = S_LEN * HID / 4;
        to_fp16_kernel<<<(n4 + 255) / 256, 256>>>(hidden, a, n4);
        int w4 = HID * NQKV / 4;
        to_fp16_kernel<<<(w4 + 255) / 256, 256>>>(W_qkv, b, w4);
        int d4 = HID * HID / 4;
        to_fp16_kernel<<<(d4 + 255) / 256, 256>>>(W_dense, w, d4);
    }

    // 1) QKV projection + bias + RoPE + scatter
    {
        dim3 grid(NQKV / 128, S_LEN / 128);
        qkv_gemm_rope<<<grid, 256, GEMM_SMEM>>>(a, b, b_qkv, qf, kf, vf);
    }

    // 2) causal flash attention (exp2 softmax, 2 CTAs/SM)
    flash_mma_kernel<<<dim3(S_LEN / FBM, NH), 128, FLASH_SMEM>>>(qf, kf, vf, c);

    // 3) dense projection (+bias) -> fp32 out
    {
        dim3 grid(HID / 128, S_LEN / 128);
        mma_gemm_dense<<<grid, 256, GEMM_SMEM>>>(c, w, b_dense, out);
    }
}

// round 17
// speedup vs baseline: 1.0316x; 1.0060x over previous
#include <cuda_runtime.h>
#include <cuda_fp16.h>
#include <cstdint>
#include <math.h>

using std::uint32_t;

// ---------------- problem constants ----------------
#define S_LEN 2048
#define HID   2048
#define NH    16
#define HD    128
#define NQKV  6144   // 3 * HID
#define ROT   32

// ---------------- scratch (device globals; no runtime alloc) ----------------
__device__ __half g_a[(size_t)S_LEN * HID];
__device__ __half g_b[(size_t)HID * NQKV];
__device__ __half g_w[(size_t)HID * HID];
__device__ __half g_c[(size_t)S_LEN * HID];

__device__ __half g_qf[(size_t)NH * S_LEN * HD];   // roped, scaled by log2e/sqrt(hd)
__device__ __half g_kf[(size_t)NH * S_LEN * HD];   // roped
__device__ __half g_vf[(size_t)NH * S_LEN * HD];

// ---------------- common PTX helpers ----------------
__device__ __forceinline__ void cp_async16(void* smem_dst, const void* gmem_src) {
    uint32_t s = (uint32_t)__cvta_generic_to_shared(smem_dst);
    asm volatile("cp.async.cg.shared.global [%0], [%1], 16;\n" :: "r"(s), "l"(gmem_src));
}
__device__ __forceinline__ void cp_commit() {
    asm volatile("cp.async.commit_group;\n");
}
template <int N>
__device__ __forceinline__ void cp_wait() {
    asm volatile("cp.async.wait_group %0;\n" :: "n"(N));
}

__device__ __forceinline__ void mma16816(float* c, const uint32_t* a, const uint32_t* b) {
    asm volatile(
        "mma.sync.aligned.m16n8k16.row.col.f32.f16.f16.f32 "
        "{%0,%1,%2,%3}, {%4,%5,%6,%7}, {%8,%9}, {%0,%1,%2,%3};\n"
        : "+f"(c[0]), "+f"(c[1]), "+f"(c[2]), "+f"(c[3])
        : "r"(a[0]), "r"(a[1]), "r"(a[2]), "r"(a[3]), "r"(b[0]), "r"(b[1]));
}

__device__ __forceinline__ void ldmx4(uint32_t* r, const void* p) {
    uint32_t a = (uint32_t)__cvta_generic_to_shared(p);
    asm volatile("ldmatrix.sync.aligned.m8n8.x4.shared.b16 {%0,%1,%2,%3}, [%4];"
                 : "=r"(r[0]), "=r"(r[1]), "=r"(r[2]), "=r"(r[3]) : "r"(a));
}
__device__ __forceinline__ void ldmx4t(uint32_t* r, const void* p) {
    uint32_t a = (uint32_t)__cvta_generic_to_shared(p);
    asm volatile("ldmatrix.sync.aligned.m8n8.x4.trans.shared.b16 {%0,%1,%2,%3}, [%4];"
                 : "=r"(r[0]), "=r"(r[1]), "=r"(r[2]), "=r"(r[3]) : "r"(a));
}

// ---------------- fp32 -> fp16 convert ----------------
__global__ __launch_bounds__(256) void to_fp16_kernel(
    const float* __restrict__ x, __half* __restrict__ y, int n4)
{
    int i = blockIdx.x * blockDim.x + threadIdx.x;
    if (i >= n4) return;
    float4 v = reinterpret_cast<const float4*>(x)[i];
    __half2* yp = reinterpret_cast<__half2*>(y);
    yp[2 * i]     = __floats2half2_rn(v.x, v.y);
    yp[2 * i + 1] = __floats2half2_rn(v.z, v.w);
}

// ---------------- GEMM tiling constants ----------------
#define GBK 64
#define SA     72
#define SB     136
#define OA     0
#define OB     (128 * SA)
#define BUFSZ  (OB + GBK * SB)       // 17920 halfs = 35840 B
#define GEMM_SMEM (3 * BUFSZ * 2)    // 107520 B

// ---------------- QKV GEMM + bias + RoPE + head-major scatter ----------------
__global__ __launch_bounds__(256, 2) void qkv_gemm_rope(
    const __half* __restrict__ A, const __half* __restrict__ B,
    const float* __restrict__ bias,
    __half* __restrict__ Qp, __half* __restrict__ Kp, __half* __restrict__ Vp)
{
    extern __shared__ __align__(16) unsigned char smraw[];
    __half* sm = reinterpret_cast<__half*>(smraw);

    const int bx = blockIdx.x;
    const int by = blockIdx.y;
    const int tid = threadIdx.x;
    const int warp = tid >> 5;
    const int lane = tid & 31;
    const int warp_m = warp & 3;
    const int warp_n = warp >> 2;
    const int g  = lane >> 2;
    const int tg = lane & 3;
    const int K = HID, N = NQKV;
    const int nst = K / GBK;

    float acc[2][8][4];
    #pragma unroll
    for (int i = 0; i < 2; i++)
        #pragma unroll
        for (int j = 0; j < 8; j++)
            #pragma unroll
            for (int x = 0; x < 4; x++) acc[i][j][x] = 0.0f;

    auto issue = [&](int s) {
        const int k0 = s * GBK;
        __half* buf = sm + (s % 3) * BUFSZ;
        #pragma unroll
        for (int p = 0; p < 4; p++) {
            int q = tid + p * 256;
            int r = q >> 3, c = q & 7;
            size_t ga = (size_t)(by * 128 + r) * K + k0 + c * 8;
            cp_async16(buf + OA + r * SA + c * 8, A + ga);
        }
        #pragma unroll
        for (int p = 0; p < 4; p++) {
            int q = tid + p * 256;
            int r = q >> 4, c = q & 15;
            size_t gb = (size_t)(k0 + r) * N + bx * 128 + c * 8;
            cp_async16(buf + OB + r * SB + c * 8, B + gb);
        }
    };

    issue(0); cp_commit();
    issue(1); cp_commit();

    const int a_row = lane & 15;
    const int a_colh = (lane >> 4) << 3;
    const int b_row = lane & 15;
    const int b_colh = (lane >> 4) << 3;

    for (int s = 0; s < nst; s++) {
        cp_wait<1>();
        __syncthreads();
        if (s + 2 < nst) { issue(s + 2); cp_commit(); }

        const __half* buf = sm + (s % 3) * BUFSZ;

        #pragma unroll
        for (int ks = 0; ks < GBK; ks += 16) {
            uint32_t ah[2][4];
            #pragma unroll
            for (int i = 0; i < 2; i++) {
                int ra = (warp_m * 32 + i * 16 + a_row) * SA + ks + a_colh;
                ldmx4(ah[i], buf + OA + ra);
            }
            #pragma unroll
            for (int jp = 0; jp < 4; jp++) {
                int rb = (ks + b_row) * SB + warp_n * 64 + jp * 16 + b_colh;
                uint32_t th[4];
                ldmx4t(th, buf + OB + rb);
                uint32_t b0[2] = {th[0], th[1]}, b1[2] = {th[2], th[3]};
                #pragma unroll
                for (int i = 0; i < 2; i++) {
                    mma16816(acc[i][2 * jp],     ah[i], b0);
                    mma16816(acc[i][2 * jp + 1], ah[i], b1);
                }
            }
        }
    }

    // ---- epilogue: bias, RoPE (q/k), scale (q), head-major scatter ----
    const int head = bx / 3;
    const int sel  = bx - head * 3;      // 0=q, 1=k, 2=v
    __half* dst = (sel == 0) ? Qp : (sel == 1) ? Kp : Vp;
    const float qscale = 0.08838834764831845f * 1.44269504088896f;  // log2e folded

    #pragma unroll
    for (int i = 0; i < 2; i++)
        #pragma unroll
        for (int j = 0; j < 8; j++) {
            int col = bx * 128 + warp_n * 64 + j * 8 + tg * 2;
            float b0 = bias[col], b1 = bias[col + 1];
            acc[i][j][0] += b0; acc[i][j][1] += b1;
            acc[i][j][2] += b0; acc[i][j][3] += b1;
        }

    if (sel < 2 && warp_n == 0) {
        #pragma unroll
        for (int i = 0; i < 2; i++) {
            int r0 = by * 128 + warp_m * 32 + i * 16 + g;
            #pragma unroll
            for (int j = 0; j < 2; j++) {
                #pragma unroll
                for (int e = 0; e < 2; e++) {
                    int d = j * 8 + tg * 2 + e;
                    float invf = powf(10000.0f, -(float)(2 * d) / 32.0f);
                    float s0, c0, s1, c1;
                    sincosf((float)r0 * invf, &s0, &c0);
                    sincosf((float)(r0 + 8) * invf, &s1, &c1);
                    float x1a = acc[i][j][e],     x2a = acc[i][j + 2][e];
                    float x1b = acc[i][j][e + 2], x2b = acc[i][j + 2][e + 2];
                    acc[i][j][e]         = x1a * c0 - x2a * s0;
                    acc[i][j + 2][e]     = x2a * c0 + x1a * s0;
                    acc[i][j][e + 2]     = x1b * c1 - x2b * s1;
                    acc[i][j + 2][e + 2] = x2b * c1 + x1b * s1;
                }
            }
        }
    }

    if (sel == 0) {
        #pragma unroll
        for (int i = 0; i < 2; i++)
            #pragma unroll
            for (int j = 0; j < 8; j++)
                #pragma unroll
                for (int x = 0; x < 4; x++) acc[i][j][x] *= qscale;
    }

    #pragma unroll
    for (int i = 0; i < 2; i++) {
        int row0 = by * 128 + warp_m * 32 + i * 16 + g;
        #pragma unroll
        for (int j = 0; j < 8; j++) {
            int d = warp_n * 64 + j * 8 + tg * 2;
            size_t o0 = ((size_t)head * S_LEN + row0) * HD + d;
            size_t o1 = ((size_t)head * S_LEN + row0 + 8) * HD + d;
            *reinterpret_cast<__half2*>(dst + o0) =
                __floats2half2_rn(acc[i][j][0], acc[i][j][1]);
            *reinterpret_cast<__half2*>(dst + o1) =
                __floats2half2_rn(acc[i][j][2], acc[i][j][3]);
        }
    }
}

// ---------------- dense GEMM (fp16 in, fp32 out + bias) ----------------
__global__ __launch_bounds__(256, 2) void mma_gemm_dense(
    const __half* __restrict__ A, const __half* __restrict__ B,
    const float* __restrict__ bias, float* __restrict__ C)
{
    extern __shared__ __align__(16) unsigned char smraw[];
    __half* sm = reinterpret_cast<__half*>(smraw);

    const int bx = blockIdx.x;
    const int by = blockIdx.y;
    const int tid = threadIdx.x;
    const int warp = tid >> 5;
    const int lane = tid & 31;
    const int warp_m = warp & 3;
    const int warp_n = warp >> 2;
    const int g  = lane >> 2;
    const int tg = lane & 3;
    const int K = HID, N = HID;
    const int nst = K / GBK;

    float acc[2][8][4];
    #pragma unroll
    for (int i = 0; i < 2; i++)
        #pragma unroll
        for (int j = 0; j < 8; j++)
            #pragma unroll
            for (int x = 0; x < 4; x++) acc[i][j][x] = 0.0f;

    auto issue = [&](int s) {
        const int k0 = s * GBK;
        __half* buf = sm + (s % 3) * BUFSZ;
        #pragma unroll
        for (int p = 0; p < 4; p++) {
            int q = tid + p * 256;
            int r = q >> 3, c = q & 7;
            size_t ga = (size_t)(by * 128 + r) * K + k0 + c * 8;
            cp_async16(buf + OA + r * SA + c * 8, A + ga);
        }
        #pragma unroll
        for (int p = 0; p < 4; p++) {
            int q = tid + p * 256;
            int r = q >> 4, c = q & 15;
            size_t gb = (size_t)(k0 + r) * N + bx * 128 + c * 8;
            cp_async16(buf + OB + r * SB + c * 8, B + gb);
        }
    };

    issue(0); cp_commit();
    issue(1); cp_commit();

    const int a_row = lane & 15;
    const int a_colh = (lane >> 4) << 3;
    const int b_row = lane & 15;
    const int b_colh = (lane >> 4) << 3;

    for (int s = 0; s < nst; s++) {
        cp_wait<1>();
        __syncthreads();
        if (s + 2 < nst) { issue(s + 2); cp_commit(); }

        const __half* buf = sm + (s % 3) * BUFSZ;

        #pragma unroll
        for (int ks = 0; ks < GBK; ks += 16) {
            uint32_t ah[2][4];
            #pragma unroll
            for (int i = 0; i < 2; i++) {
                int ra = (warp_m * 32 + i * 16 + a_row) * SA + ks + a_colh;
                ldmx4(ah[i], buf + OA + ra);
            }
            #pragma unroll
            for (int jp = 0; jp < 4; jp++) {
                int rb = (ks + b_row) * SB + warp_n * 64 + jp * 16 + b_colh;
                uint32_t th[4];
                ldmx4t(th, buf + OB + rb);
                uint32_t b0[2] = {th[0], th[1]}, b1[2] = {th[2], th[3]};
                #pragma unroll
                for (int i = 0; i < 2; i++) {
                    mma16816(acc[i][2 * jp],     ah[i], b0);
                    mma16816(acc[i][2 * jp + 1], ah[i], b1);
                }
            }
        }
    }

    #pragma unroll
    for (int i = 0; i < 2; i++) {
        #pragma unroll
        for (int j = 0; j < 8; j++) {
            int row0 = by * 128 + warp_m * 32 + i * 16 + g;
            int col  = bx * 128 + warp_n * 64 + j * 8 + tg * 2;
            float b0 = bias[col], b1 = bias[col + 1];
            *reinterpret_cast<float2*>(C + (size_t)row0 * N + col) =
                make_float2(acc[i][j][0] + b0, acc[i][j][1] + b1);
            *reinterpret_cast<float2*>(C + (size_t)(row0 + 8) * N + col) =
                make_float2(acc[i][j][2] + b0, acc[i][j][3] + b1);
        }
    }
}

// ---------------- HMMA flash attention (fp16, causal, Q in registers) ----------------
// FBM=64, FBN=64, 128 threads (4 warps), 2 CTAs/SM.
#define FBM 64
#define FBN 64
#define FSTR 136

#define FQ    0
#define FKV0  (64 * FSTR)            // 8704 halfs
#define KVARR (64 * FSTR)
#define KVSTG (2 * KVARR)
#define FLASH_SMEM ((FKV0 + 2 * KVSTG) * 2)   // 87040 B

__global__ __launch_bounds__(128, 2) void flash_mma_kernel(
    const __half* __restrict__ Q, const __half* __restrict__ K,
    const __half* __restrict__ V, __half* __restrict__ Cf)
{
    extern __shared__ __align__(16) unsigned char fsraw[];
    __half* fs = reinterpret_cast<__half*>(fsraw);

    const int h = blockIdx.y;
    const int m_tile = gridDim.x - 1 - blockIdx.x;
    const int m0 = m_tile * FBM;
    const int tid = threadIdx.x;
    const int warp = tid >> 5;
    const int lane = tid & 31;
    const int g  = lane >> 2;
    const int tg = lane & 3;

    const __half* qp = Q + ((size_t)h * S_LEN + m0) * HD;
    const __half* kp = K + (size_t)h * S_LEN * HD;
    const __half* vp = V + (size_t)h * S_LEN * HD;

    // stage Q tile once
    for (int idx = tid; idx < 1024; idx += 128) {
        int r = idx >> 4, c = (idx & 15) << 3;
        *reinterpret_cast<float4*>(fs + FQ + r * FSTR + c) =
            *reinterpret_cast<const float4*>(qp + (size_t)r * HD + c);
    }

    auto issue_kv = [&](int nt) {
        const int n0 = nt * FBN;
        __half* buf = fs + FKV0 + (nt & 1) * KVSTG;
        #pragma unroll
        for (int q = tid; q < 1024; q += 128) {
            int r = q >> 4, c = (q & 15) << 3;
            size_t go = (size_t)(n0 + r) * HD + c;
            int so = r * FSTR + c;
            cp_async16(buf + 0 * KVARR + so, kp + go);
            cp_async16(buf + 1 * KVARR + so, vp + go);
        }
    };

    const int a_row = lane & 15;
    const int half8 = (lane >> 4) << 3;
    const int bk_colh = ((lane >> 3) & 1) << 3;

    issue_kv(0); cp_commit();
    __syncthreads();   // Q stage visible

    // load Q fragments into registers ONCE (reused every KV tile)
    uint32_t qF[8][4];
    #pragma unroll
    for (int ks = 0; ks < 8; ks++) {
        int ra = (warp * 16 + a_row) * FSTR + ks * 16 + half8;
        ldmx4(qF[ks], fs + FQ + ra);
    }

    float o[16][4];
    #pragma unroll
    for (int j = 0; j < 16; j++)
        #pragma unroll
        for (int x = 0; x < 4; x++) o[j][x] = 0.0f;
    float mrow0 = -1e30f, mrow1 = -1e30f, lrow0 = 0.0f, lrow1 = 0.0f;

    const int row0 = m0 + warp * 16 + g;
    const int row1 = row0 + 8;

    const int ntiles = m0 / FBN + 1;

    for (int nt = 0; nt < ntiles; nt++) {
        const int n0 = nt * FBN;
        if (nt + 1 < ntiles) { issue_kv(nt + 1); cp_commit(); cp_wait<1>(); }
        else                 { cp_wait<0>(); }
        __syncthreads();

        const __half* kvb = fs + FKV0 + (nt & 1) * KVSTG;
        const __half* k_s = kvb;
        const __half* v_s = kvb + KVARR;

        float sacc[8][4];
        #pragma unroll
        for (int j = 0; j < 8; j++)
            #pragma unroll
            for (int x = 0; x < 4; x++) sacc[j][x] = 0.0f;

        #pragma unroll
        for (int ks = 0; ks < 8; ks++) {
            const int k = ks * 16;
            #pragma unroll
            for (int jp = 0; jp < 4; jp++) {
                int rb = (jp * 16 + half8 + (lane & 7)) * FSTR + k + bk_colh;
                uint32_t bF[4];
                ldmx4(bF, k_s + rb);
                uint32_t b0[2] = {bF[0], bF[1]}, b1[2] = {bF[2], bF[3]};
                mma16816(sacc[2 * jp],     qF[ks], b0);
                mma16816(sacc[2 * jp + 1], qF[ks], b1);
            }
        }

        if (nt == ntiles - 1) {
            #pragma unroll
            for (int j = 0; j < 8; j++) {
                int c0 = n0 + j * 8 + 2 * tg;
                if (c0     > row0) sacc[j][0] = -1e30f;
                if (c0 + 1 > row0) sacc[j][1] = -1e30f;
                if (c0     > row1) sacc[j][2] = -1e30f;
                if (c0 + 1 > row1) sacc[j][3] = -1e30f;
            }
        }

        float mx0 = -1e30f, mx1 = -1e30f;
        #pragma unroll
        for (int j = 0; j < 8; j++) {
            mx0 = fmaxf(mx0, fmaxf(sacc[j][0], sacc[j][1]));
            mx1 = fmaxf(mx1, fmaxf(sacc[j][2], sacc[j][3]));
        }
        mx0 = fmaxf(mx0, __shfl_xor_sync(0xffffffffu, mx0, 1));
        mx0 = fmaxf(mx0, __shfl_xor_sync(0xffffffffu, mx0, 2));
        mx1 = fmaxf(mx1, __shfl_xor_sync(0xffffffffu, mx1, 1));
        mx1 = fmaxf(mx1, __shfl_xor_sync(0xffffffffu, mx1, 2));

        float mn0 = fmaxf(mrow0, mx0);
        float mn1 = fmaxf(mrow1, mx1);
        float alpha0 = exp2f(mrow0 - mn0);
        float alpha1 = exp2f(mrow1 - mn1);
        mrow0 = mn0; mrow1 = mn1;

        float sum0 = 0.0f, sum1 = 0.0f;
        #pragma unroll
        for (int j = 0; j < 8; j++) {
            sacc[j][0] = exp2f(sacc[j][0] - mn0);
            sacc[j][1] = exp2f(sacc[j][1] - mn0);
            sacc[j][2] = exp2f(sacc[j][2] - mn1);
            sacc[j][3] = exp2f(sacc[j][3] - mn1);
            sum0 += sacc[j][0] + sacc[j][1];
            sum1 += sacc[j][2] + sacc[j][3];
        }
        sum0 += __shfl_xor_sync(0xffffffffu, sum0, 1);
        sum0 += __shfl_xor_sync(0xffffffffu, sum0, 2);
        sum1 += __shfl_xor_sync(0xffffffffu, sum1, 1);
        sum1 += __shfl_xor_sync(0xffffffffu, sum1, 2);
        lrow0 = lrow0 * alpha0 + sum0;
        lrow1 = lrow1 * alpha1 + sum1;

        #pragma unroll
        for (int j = 0; j < 16; j++) {
            o[j][0] *= alpha0; o[j][1] *= alpha0;
            o[j][2] *= alpha1; o[j][3] *= alpha1;
        }

        #pragma unroll
        for (int kk = 0; kk < 4; kk++) {
            uint32_t pa[4];
            #pragma unroll
            for (int half = 0; half < 2; half++) {
                const float* sv = sacc[2 * kk + half];
                __half2 h0 = __floats2half2_rn(sv[0], sv[1]);
                __half2 h1 = __floats2half2_rn(sv[2], sv[3]);
                pa[2 * half]     = *reinterpret_cast<uint32_t*>(&h0);
                pa[2 * half + 1] = *reinterpret_cast<uint32_t*>(&h1);
            }
            #pragma unroll
            for (int jp = 0; jp < 8; jp++) {
                int rv = (kk * 16 + a_row) * FSTR + jp * 16 + half8;
                uint32_t vF[4];
                ldmx4t(vF, v_s + rv);
                uint32_t v0[2] = {vF[0], vF[1]}, v1[2] = {vF[2], vF[3]};
                mma16816(o[2 * jp],     pa, v0);
                mma16816(o[2 * jp + 1], pa, v1);
            }
        }
        __syncthreads();
    }

    float inv0 = 1.0f / lrow0;
    float inv1 = 1.0f / lrow1;
    #pragma unroll
    for (int jt = 0; jt < 16; jt++) {
        int col = h * HD + jt * 8 + 2 * tg;
        __half2 r0 = __floats2half2_rn(o[jt][0] * inv0, o[jt][1] * inv0);
        __half2 r1 = __floats2half2_rn(o[jt][2] * inv1, o[jt][3] * inv1);
        *reinterpret_cast<__half2*>(Cf + (size_t)row0 * HID + col) = r0;
        *reinterpret_cast<__half2*>(Cf + (size_t)row1 * HID + col) = r1;
    }
}

// ---------------- launch ----------------
extern "C" void kernel_launch(void* const* d_in, const int* in_sizes, int n_in,
                              void* d_out, int out_size)
{
    const float* hidden  = (const float*)d_in[0];
    const float* W_qkv   = (const float*)d_in[1];
    const float* b_qkv   = (const float*)d_in[2];
    const float* W_dense = (const float*)d_in[3];
    const float* b_dense = (const float*)d_in[4];
    float* out = (float*)d_out;

    __half *a, *b, *w, *c, *qf, *kf, *vf;
    cudaGetSymbolAddress((void**)&a,  g_a);
    cudaGetSymbolAddress((void**)&b,  g_b);
    cudaGetSymbolAddress((void**)&w,  g_w);
    cudaGetSymbolAddress((void**)&c,  g_c);
    cudaGetSymbolAddress((void**)&qf, g_qf);
    cudaGetSymbolAddress((void**)&kf, g_kf);
    cudaGetSymbolAddress((void**)&vf, g_vf);

    cudaFuncSetAttribute(qkv_gemm_rope,
                         cudaFuncAttributeMaxDynamicSharedMemorySize, GEMM_SMEM);
    cudaFuncSetAttribute(mma_gemm_dense,
                         cudaFuncAttributeMaxDynamicSharedMemorySize, GEMM_SMEM);
    cudaFuncSetAttribute(flash_mma_kernel,
                         cudaFuncAttributeMaxDynamicSharedMemorySize, FLASH_SMEM);

    // 0) fp16 conversions
    {
        int n4 = S_LEN * HID / 4;
        to_fp16_kernel<<<(n4 + 255) / 256, 256>>>(hidden, a, n4);
        int w4 = HID * NQKV / 4;
        to_fp16_kernel<<<(w4 + 255) / 256, 256>>>(W_qkv, b, w4);
        int d4 = HID * HID / 4;
        to_fp16_kernel<<<(d4 + 255) / 256, 256>>>(W_dense, w, d4);
    }

    // 1) QKV projection + bias + RoPE + scatter
    {
        dim3 grid(NQKV / 128, S_LEN / 128);
        qkv_gemm_rope<<<grid, 256, GEMM_SMEM>>>(a, b, b_qkv, qf, kf, vf);
    }

    // 2) causal flash attention (exp2, Q in registers, 2 CTAs/SM)
    flash_mma_kernel<<<dim3(S_LEN / FBM, NH), 128, FLASH_SMEM>>>(qf, kf, vf, c);

    // 3) dense projection (+bias) -> fp32 out
    {
        dim3 grid(HID / 128, S_LEN / 128);
        mma_gemm_dense<<<grid, 256, GEMM_SMEM>>>(c, w, b_dense, out);
    }
}